// round 1
// baseline (speedup 1.0000x reference)
#include <cuda_runtime.h>
#include <cuda_bf16.h>
#include <math.h>

// ---------------- problem constants ----------------
constexpr int D_MODEL = 1024;
constexpr int NH      = 16;
constexpr int HD      = 64;
constexpr int BB      = 8;
constexpr int SS      = 2048;
constexpr int MROWS   = BB * SS;          // 16384
constexpr int NGATES  = 48;               // i(16) f(16) o(16)
constexpr float GATE_CAP = 15.0f;
constexpr float EPS = 1e-5f;

constexpr size_t Y_ELEMS = (size_t)MROWS * D_MODEL;          // 16,777,216
constexpr size_t H_ELEMS = (size_t)BB * NH * HD * HD;        //    524,288

// ---------------- device scratch (no allocation allowed) ----------------
__device__ float g_xn[MROWS * D_MODEL];
__device__ float g_q [MROWS * D_MODEL];
__device__ float g_k [MROWS * D_MODEL];
__device__ float g_v [MROWS * D_MODEL];
__device__ float g_h [MROWS * D_MODEL];
__device__ float g_gates[MROWS * NGATES];
__device__ float g_Hdump[BB * NH * HD * HD];

// ---------------- RMSNorm: x -> g_xn ----------------
__global__ __launch_bounds__(256)
void rmsnorm_kernel(const float* __restrict__ x, const float* __restrict__ w)
{
    int row = blockIdx.x;
    int t = threadIdx.x;                       // 256 threads, 4 floats each
    const float4* xr = (const float4*)(x + (size_t)row * D_MODEL);
    float4 v = xr[t];
    float ss = v.x*v.x + v.y*v.y + v.z*v.z + v.w*v.w;
    #pragma unroll
    for (int o = 16; o; o >>= 1) ss += __shfl_xor_sync(0xffffffffu, ss, o);
    __shared__ float sred[8];
    if ((t & 31) == 0) sred[t >> 5] = ss;
    __syncthreads();
    if (t < 8) {
        float s = sred[t];
        #pragma unroll
        for (int o = 4; o; o >>= 1) s += __shfl_xor_sync(0xffu, s, o);
        if (t == 0) sred[0] = s;
    }
    __syncthreads();
    float inv = rsqrtf(sred[0] * (1.0f / D_MODEL) + EPS);
    const float4* wr = (const float4*)w;
    float4 wv = wr[t];
    float4 o4;
    o4.x = v.x * inv * wv.x;
    o4.y = v.y * inv * wv.y;
    o4.z = v.z * inv * wv.z;
    o4.w = v.w * inv * wv.w;
    ((float4*)(g_xn + (size_t)row * D_MODEL))[t] = o4;
}

// ---------------- SGEMM: C[M,N] = A[M,K] * B[N,K]^T (+residual) ----------------
// MODE: 0 -> A=g_xn, C=g_q ; 1 -> A=g_xn, C=g_k ; 2 -> A=g_xn, C=g_v
//       3 -> A=g_h,  C=Cext, + residual Res
constexpr int BM = 128, BN = 128, BK = 16;

template<int MODE>
__global__ __launch_bounds__(256, 2)
void sgemm_kernel(const float* __restrict__ B, float* __restrict__ Cext,
                  const float* __restrict__ Res)
{
    constexpr int K = D_MODEL;
    constexpr int N = D_MODEL;

    const float* A;
    float* C;
    if      (MODE == 0) { A = g_xn; C = g_q;  }
    else if (MODE == 1) { A = g_xn; C = g_k;  }
    else if (MODE == 2) { A = g_xn; C = g_v;  }
    else                { A = g_h;  C = Cext; }

    __shared__ __align__(16) float As[2][BK][BM + 4];
    __shared__ __align__(16) float Bs[2][BK][BN + 4];

    const int tid = threadIdx.x;
    const int bm = blockIdx.y * BM;
    const int bn = blockIdx.x * BN;

    const int arow = tid >> 2;            // 0..63
    const int acol = (tid & 3) << 2;      // 0,4,8,12
    const float* Aa = A + (size_t)(bm + arow) * K + acol;
    const float* Bb = B + (size_t)(bn + arow) * K + acol;

    // prologue: tile 0
    float4 pa0 = *(const float4*)(Aa);
    float4 pa1 = *(const float4*)(Aa + (size_t)64 * K);
    float4 pb0 = *(const float4*)(Bb);
    float4 pb1 = *(const float4*)(Bb + (size_t)64 * K);
    {
        float (*An)[BM + 4] = As[0];
        float (*Bn)[BN + 4] = Bs[0];
        An[acol+0][arow] = pa0.x; An[acol+1][arow] = pa0.y;
        An[acol+2][arow] = pa0.z; An[acol+3][arow] = pa0.w;
        An[acol+0][arow+64] = pa1.x; An[acol+1][arow+64] = pa1.y;
        An[acol+2][arow+64] = pa1.z; An[acol+3][arow+64] = pa1.w;
        Bn[acol+0][arow] = pb0.x; Bn[acol+1][arow] = pb0.y;
        Bn[acol+2][arow] = pb0.z; Bn[acol+3][arow] = pb0.w;
        Bn[acol+0][arow+64] = pb1.x; Bn[acol+1][arow+64] = pb1.y;
        Bn[acol+2][arow+64] = pb1.z; Bn[acol+3][arow+64] = pb1.w;
    }
    __syncthreads();

    const int tx = tid & 15, ty = tid >> 4;
    const int m0 = ty * 4, m1 = ty * 4 + 64;
    const int n0 = tx * 4, n1 = tx * 4 + 64;

    float acc[8][8];
    #pragma unroll
    for (int i = 0; i < 8; ++i)
        #pragma unroll
        for (int j = 0; j < 8; ++j) acc[i][j] = 0.0f;

    constexpr int KT = K / BK;   // 64
    int cur = 0;
    for (int kt = 0; kt < KT; ++kt) {
        if (kt + 1 < KT) {
            const float* Ain = Aa + (kt + 1) * BK;
            const float* Bin = Bb + (kt + 1) * BK;
            pa0 = *(const float4*)(Ain);
            pa1 = *(const float4*)(Ain + (size_t)64 * K);
            pb0 = *(const float4*)(Bin);
            pb1 = *(const float4*)(Bin + (size_t)64 * K);
        }
        const float (*Asc)[BM + 4] = As[cur];
        const float (*Bsc)[BN + 4] = Bs[cur];
        #pragma unroll
        for (int k = 0; k < BK; ++k) {
            float4 a0 = *(const float4*)&Asc[k][m0];
            float4 a1 = *(const float4*)&Asc[k][m1];
            float4 b0 = *(const float4*)&Bsc[k][n0];
            float4 b1 = *(const float4*)&Bsc[k][n1];
            float av[8] = {a0.x,a0.y,a0.z,a0.w,a1.x,a1.y,a1.z,a1.w};
            float bv[8] = {b0.x,b0.y,b0.z,b0.w,b1.x,b1.y,b1.z,b1.w};
            #pragma unroll
            for (int i = 0; i < 8; ++i)
                #pragma unroll
                for (int j = 0; j < 8; ++j)
                    acc[i][j] = fmaf(av[i], bv[j], acc[i][j]);
        }
        if (kt + 1 < KT) {
            int nxt = cur ^ 1;
            float (*An)[BM + 4] = As[nxt];
            float (*Bn)[BN + 4] = Bs[nxt];
            An[acol+0][arow] = pa0.x; An[acol+1][arow] = pa0.y;
            An[acol+2][arow] = pa0.z; An[acol+3][arow] = pa0.w;
            An[acol+0][arow+64] = pa1.x; An[acol+1][arow+64] = pa1.y;
            An[acol+2][arow+64] = pa1.z; An[acol+3][arow+64] = pa1.w;
            Bn[acol+0][arow] = pb0.x; Bn[acol+1][arow] = pb0.y;
            Bn[acol+2][arow] = pb0.z; Bn[acol+3][arow] = pb0.w;
            Bn[acol+0][arow+64] = pb1.x; Bn[acol+1][arow+64] = pb1.y;
            Bn[acol+2][arow+64] = pb1.z; Bn[acol+3][arow+64] = pb1.w;
            __syncthreads();
            cur = nxt;
        }
    }

    // epilogue
    #pragma unroll
    for (int i = 0; i < 8; ++i) {
        int m = bm + ((i < 4) ? (m0 + i) : (m1 + i - 4));
        float* cp = C + (size_t)m * N + bn;
        float4 c0 = make_float4(acc[i][0], acc[i][1], acc[i][2], acc[i][3]);
        float4 c1 = make_float4(acc[i][4], acc[i][5], acc[i][6], acc[i][7]);
        if (MODE == 3) {
            const float* rp = Res + (size_t)m * N + bn;
            float4 r0 = *(const float4*)(rp + n0);
            float4 r1 = *(const float4*)(rp + n1);
            c0.x += r0.x; c0.y += r0.y; c0.z += r0.z; c0.w += r0.w;
            c1.x += r1.x; c1.y += r1.y; c1.z += r1.z; c1.w += r1.w;
        }
        *(float4*)(cp + n0) = c0;
        *(float4*)(cp + n1) = c1;
    }
}

// ---------------- gate GEMM: g_gates[row, 48] = act(g_xn @ [Wi;Wf;Wo]^T) ----------------
__global__ __launch_bounds__(256)
void gates_kernel(const float* __restrict__ Wi, const float* __restrict__ Wf,
                  const float* __restrict__ Wo)
{
    __shared__ float xs[32][132];
    __shared__ float ws[32][NGATES];
    const int tid = threadIdx.x;
    const int row0 = blockIdx.x * 128;

    const int tx = tid & 15, ty = tid >> 4;
    const int c0 = tx * 3;        // 3 gate cols per thread (48 total)
    const int r0 = ty * 8;        // 8 rows per thread

    float acc[8][3];
    #pragma unroll
    for (int r = 0; r < 8; ++r) { acc[r][0]=0.f; acc[r][1]=0.f; acc[r][2]=0.f; }

    for (int k0 = 0; k0 < D_MODEL; k0 += 32) {
        #pragma unroll
        for (int i = 0; i < 4; ++i) {
            int idx4 = tid + i * 256;           // 0..1023 (float4 units)
            int r = idx4 >> 3;                  // row 0..127
            int c4 = (idx4 & 7) << 2;           // k 0..28 step 4
            float4 v = *(const float4*)(g_xn + (size_t)(row0 + r) * D_MODEL + k0 + c4);
            xs[c4+0][r] = v.x; xs[c4+1][r] = v.y; xs[c4+2][r] = v.z; xs[c4+3][r] = v.w;
        }
        #pragma unroll
        for (int i = 0; i < 6; ++i) {
            int idx = tid + i * 256;            // 0..1535
            int j = idx >> 5;                   // gate col 0..47
            int kk = idx & 31;
            const float* Wg = (j < 16) ? (Wi + (size_t)j * D_MODEL)
                            : (j < 32) ? (Wf + (size_t)(j - 16) * D_MODEL)
                                       : (Wo + (size_t)(j - 32) * D_MODEL);
            ws[kk][j] = Wg[k0 + kk];
        }
        __syncthreads();
        #pragma unroll
        for (int k = 0; k < 32; ++k) {
            float b0 = ws[k][c0], b1 = ws[k][c0+1], b2 = ws[k][c0+2];
            #pragma unroll
            for (int r = 0; r < 8; ++r) {
                float a = xs[k][r0 + r];
                acc[r][0] = fmaf(a, b0, acc[r][0]);
                acc[r][1] = fmaf(a, b1, acc[r][1]);
                acc[r][2] = fmaf(a, b2, acc[r][2]);
            }
        }
        __syncthreads();
    }
    #pragma unroll
    for (int r = 0; r < 8; ++r) {
        #pragma unroll
        for (int c = 0; c < 3; ++c) {
            float z = acc[r][c];
            float g = GATE_CAP * tanhf(z * (1.0f / GATE_CAP));
            g = 1.0f / (1.0f + expf(-g));
            g_gates[(size_t)(row0 + r0 + r) * NGATES + c0 + c] = g;
        }
    }
}

// ---------------- sequential mLSTM scan ----------------
// grid (NH, BB), 64 threads. Thread e owns column H[:, e] (64 regs).
__global__ __launch_bounds__(64)
void scan_kernel(float* __restrict__ Hfin)
{
    const int h = blockIdx.x;
    const int b = blockIdx.y;
    const int e = threadIdx.x;

    float H[HD];
    #pragma unroll
    for (int d = 0; d < HD; ++d) H[d] = 0.0f;

    __shared__ __align__(16) float sq[HD];
    __shared__ __align__(16) float sk[HD];

    const size_t rbase = (size_t)b * SS;
    const int col = h * HD + e;
    const float* qp = g_q + rbase * D_MODEL + col;
    const float* kp = g_k + rbase * D_MODEL + col;
    const float* vp = g_v + rbase * D_MODEL + col;
    const float* gp = g_gates + rbase * NGATES;
    float* hp = g_h + rbase * D_MODEL + col;

    // prefetch t=0
    float qv = qp[0], kv = kp[0], vv = vp[0];
    float ig = gp[h], fg = gp[16 + h], og = gp[32 + h];

    for (int t = 0; t < SS; ++t) {
        sq[e] = qv; sk[e] = kv;
        const float ivv = ig * vv;
        const float fgc = fg;
        const float ogc = og;
        __syncthreads();
        if (t + 1 < SS) {             // prefetch next step while computing
            size_t o = (size_t)(t + 1) * D_MODEL;
            qv = qp[o]; kv = kp[o]; vv = vp[o];
            int go = (t + 1) * NGATES;
            ig = gp[go + h]; fg = gp[go + 16 + h]; og = gp[go + 32 + h];
        }
        float a0 = 0.f, a1 = 0.f, a2 = 0.f, a3 = 0.f;
        #pragma unroll
        for (int d = 0; d < HD; d += 4) {
            float4 kk = *(const float4*)&sk[d];
            float4 qq = *(const float4*)&sq[d];
            H[d+0] = fmaf(ivv, kk.x, fgc * H[d+0]); a0 = fmaf(qq.x, H[d+0], a0);
            H[d+1] = fmaf(ivv, kk.y, fgc * H[d+1]); a1 = fmaf(qq.y, H[d+1], a1);
            H[d+2] = fmaf(ivv, kk.z, fgc * H[d+2]); a2 = fmaf(qq.z, H[d+2], a2);
            H[d+3] = fmaf(ivv, kk.w, fgc * H[d+3]); a3 = fmaf(qq.w, H[d+3], a3);
        }
        hp[(size_t)t * D_MODEL] = ogc * ((a0 + a1) + (a2 + a3));
        __syncthreads();
    }

    // H_final[b][h][d][e]
    float* Hf = (Hfin ? Hfin : g_Hdump) + (((size_t)b * NH + h) * HD) * HD;
    #pragma unroll
    for (int d = 0; d < HD; ++d) Hf[d * HD + e] = H[d];
}

// ---------------- launcher ----------------
extern "C" void kernel_launch(void* const* d_in, const int* in_sizes, int n_in,
                              void* d_out, int out_size)
{
    const float* x    = (const float*)d_in[0];
    const float* Wq   = (const float*)d_in[1];
    const float* Wk   = (const float*)d_in[2];
    const float* Wv   = (const float*)d_in[3];
    const float* Wi   = (const float*)d_in[4];
    const float* Wf   = (const float*)d_in[5];
    const float* Wo   = (const float*)d_in[6];
    const float* Wout = (const float*)d_in[7];
    const float* lnw  = (const float*)d_in[8];

    float* y = (float*)d_out;
    float* Hfin = ((size_t)out_size >= Y_ELEMS + H_ELEMS) ? (y + Y_ELEMS) : nullptr;

    rmsnorm_kernel<<<MROWS, 256>>>(x, lnw);

    dim3 ggrid(D_MODEL / BN, MROWS / BM);     // (8, 128)
    sgemm_kernel<0><<<ggrid, 256>>>(Wq, nullptr, nullptr);
    sgemm_kernel<1><<<ggrid, 256>>>(Wk, nullptr, nullptr);
    sgemm_kernel<2><<<ggrid, 256>>>(Wv, nullptr, nullptr);
    gates_kernel<<<MROWS / 128, 256>>>(Wi, Wf, Wo);

    scan_kernel<<<dim3(NH, BB), 64>>>(Hfin);

    sgemm_kernel<3><<<ggrid, 256>>>(Wout, y, x);
}

// round 3
// speedup vs baseline: 1.4447x; 1.4447x over previous
#include <cuda_runtime.h>
#include <cuda_bf16.h>
#include <math.h>
#include <cstdint>

// ---------------- problem constants ----------------
constexpr int D_MODEL = 1024;
constexpr int NH      = 16;
constexpr int HD      = 64;
constexpr int BB      = 8;
constexpr int SS      = 2048;
constexpr int MROWS   = BB * SS;          // 16384
constexpr int NGATES  = 48;
constexpr float GATE_CAP = 15.0f;
constexpr float EPS = 1e-5f;

constexpr size_t Y_ELEMS = (size_t)MROWS * D_MODEL;
constexpr size_t H_ELEMS = (size_t)BB * NH * HD * HD;

// split-precision K concat: A' = [hi|lo|hi], B' = [hi|hi|lo]  -> K' = 3072
constexpr int K2 = 3 * D_MODEL;           // 3072

// GEMM tiling
constexpr int BM = 128, BN = 128, BK = 32;
constexpr int NKT = K2 / BK;              // 96
constexpr int SROW = 40;                  // smem row stride (bf16) -> 80B, conflict-free ldmatrix

// ---------------- device scratch ----------------
__device__ float g_xn[MROWS * D_MODEL];
__device__ float g_q [MROWS * D_MODEL];
__device__ float g_k [MROWS * D_MODEL];
__device__ float g_v [MROWS * D_MODEL];
__device__ float g_h [MROWS * D_MODEL];
__device__ float g_gates[MROWS * NGATES];
__device__ float g_Hdump[BB * NH * HD * HD];

__device__ __nv_bfloat16 g_Axn[(size_t)MROWS * K2];      // 96 MB
__device__ __nv_bfloat16 g_Ah [(size_t)MROWS * K2];      // 96 MB
__device__ __nv_bfloat16 g_Bq [(size_t)D_MODEL * K2];    // 6 MB
__device__ __nv_bfloat16 g_Bk [(size_t)D_MODEL * K2];
__device__ __nv_bfloat16 g_Bv [(size_t)D_MODEL * K2];
__device__ __nv_bfloat16 g_Bo [(size_t)D_MODEL * K2];

// ---------------- helpers ----------------
__device__ __forceinline__ uint32_t smem_u32(const void* p) {
    uint32_t a;
    asm("{ .reg .u64 t; cvta.to.shared.u64 t, %1; cvt.u32.u64 %0, t; }" : "=r"(a) : "l"(p));
    return a;
}
__device__ __forceinline__ void cp16(void* sdst, const void* gsrc) {
    uint32_t d = smem_u32(sdst);
    asm volatile("cp.async.cg.shared.global [%0], [%1], 16;" :: "r"(d), "l"(gsrc) : "memory");
}
__device__ __forceinline__ void ldsm_x4(uint32_t& r0, uint32_t& r1, uint32_t& r2, uint32_t& r3,
                                        uint32_t addr) {
    asm volatile("ldmatrix.sync.aligned.m8n8.x4.shared.b16 {%0,%1,%2,%3}, [%4];"
                 : "=r"(r0), "=r"(r1), "=r"(r2), "=r"(r3) : "r"(addr));
}
__device__ __forceinline__ void mma16816(float* c, const uint32_t* a, const uint32_t* b) {
    asm volatile(
        "mma.sync.aligned.m16n8k16.row.col.f32.bf16.bf16.f32 "
        "{%0,%1,%2,%3}, {%4,%5,%6,%7}, {%8,%9}, {%0,%1,%2,%3};"
        : "+f"(c[0]), "+f"(c[1]), "+f"(c[2]), "+f"(c[3])
        : "r"(a[0]), "r"(a[1]), "r"(a[2]), "r"(a[3]), "r"(b[0]), "r"(b[1]));
}

// ---------------- RMSNorm: x -> g_xn ----------------
__global__ __launch_bounds__(256)
void rmsnorm_kernel(const float* __restrict__ x, const float* __restrict__ w)
{
    int row = blockIdx.x;
    int t = threadIdx.x;
    const float4* xr = (const float4*)(x + (size_t)row * D_MODEL);
    float4 v = xr[t];
    float ss = v.x*v.x + v.y*v.y + v.z*v.z + v.w*v.w;
    #pragma unroll
    for (int o = 16; o; o >>= 1) ss += __shfl_xor_sync(0xffffffffu, ss, o);
    __shared__ float sred[8];
    if ((t & 31) == 0) sred[t >> 5] = ss;
    __syncthreads();
    if (t < 8) {
        float s = sred[t];
        #pragma unroll
        for (int o = 4; o; o >>= 1) s += __shfl_xor_sync(0xffu, s, o);
        if (t == 0) sred[0] = s;
    }
    __syncthreads();
    float inv = rsqrtf(sred[0] * (1.0f / D_MODEL) + EPS);
    const float4* wr = (const float4*)w;
    float4 wv = wr[t];
    float4 o4;
    o4.x = v.x * inv * wv.x; o4.y = v.y * inv * wv.y;
    o4.z = v.z * inv * wv.z; o4.w = v.w * inv * wv.w;
    ((float4*)(g_xn + (size_t)row * D_MODEL))[t] = o4;
}

// ---------------- fp32 -> bf16 hi/lo concat along K ----------------
// VARIANT 0 (A-side): cols [0,1024)=hi  [1024,2048)=lo  [2048,3072)=hi
// VARIANT 1 (B-side): cols [0,1024)=hi  [1024,2048)=hi  [2048,3072)=lo
template<int VARIANT>
__global__ __launch_bounds__(256)
void convert_hilo_kernel(const float* __restrict__ src, __nv_bfloat16* __restrict__ dst)
{
    int idx = blockIdx.x * blockDim.x + threadIdx.x;   // one per 8 elems
    int r   = idx >> 7;
    int k0  = (idx & 127) << 3;
    const float4* sp = (const float4*)(src + (size_t)r * D_MODEL + k0);
    float4 v0 = sp[0], v1 = sp[1];
    float f[8] = {v0.x, v0.y, v0.z, v0.w, v1.x, v1.y, v1.z, v1.w};
    __nv_bfloat16 hi[8], lo[8];
    #pragma unroll
    for (int i = 0; i < 8; ++i) {
        hi[i] = __float2bfloat16(f[i]);
        lo[i] = __float2bfloat16(f[i] - __bfloat162float(hi[i]));
    }
    uint4 H = *(uint4*)hi;
    uint4 L = *(uint4*)lo;
    __nv_bfloat16* rp = dst + (size_t)r * K2 + k0;
    if (VARIANT == 0) {
        *(uint4*)(rp)              = H;
        *(uint4*)(rp + D_MODEL)    = L;
        *(uint4*)(rp + 2*D_MODEL)  = H;
    } else {
        *(uint4*)(rp)              = H;
        *(uint4*)(rp + D_MODEL)    = H;
        *(uint4*)(rp + 2*D_MODEL)  = L;
    }
}

// ---------------- HMMA GEMM: C[M,1024] = A'[M,K2] * B'[1024,K2]^T (+Res) ----------------
// grid (1024/BN, M/BM), 256 threads = 8 warps (4m x 2n), warp tile 32x64.
__global__ __launch_bounds__(256, 2)
void gemm_hmma(const __nv_bfloat16* __restrict__ A, const __nv_bfloat16* __restrict__ B,
               float* __restrict__ C, const float* __restrict__ Res)
{
    __shared__ __align__(16) __nv_bfloat16 As[2][BM][SROW];
    __shared__ __align__(16) __nv_bfloat16 Bs[2][BN][SROW];

    const int tid = threadIdx.x;
    const int wid = tid >> 5, lane = tid & 31;
    const int bm = blockIdx.y * BM, bn = blockIdx.x * BN;
    const int wm = (wid >> 1) * 32;     // 0,32,64,96
    const int wn = (wid & 1) * 64;      // 0,64

    const __nv_bfloat16* Ag = A + (size_t)bm * K2;
    const __nv_bfloat16* Bg = B + (size_t)bn * K2;

    // per-thread load coords (2 x 16B chunks per tile per matrix)
    int r0l = tid >> 2;                 // +0 / +64 via i
    int c0l = (tid & 3) * 8;

    auto load_tile = [&](int s, int kt) {
        const __nv_bfloat16* Aa = Ag + (size_t)kt * BK;
        const __nv_bfloat16* Bb = Bg + (size_t)kt * BK;
        #pragma unroll
        for (int i = 0; i < 2; ++i) {
            int r = r0l + i * 64;
            cp16(&As[s][r][c0l], Aa + (size_t)r * K2 + c0l);
            cp16(&Bs[s][r][c0l], Bb + (size_t)r * K2 + c0l);
        }
        asm volatile("cp.async.commit_group;" ::: "memory");
    };

    float acc[2][8][4];
    #pragma unroll
    for (int mt = 0; mt < 2; ++mt)
        #pragma unroll
        for (int nt = 0; nt < 8; ++nt)
            #pragma unroll
            for (int j = 0; j < 4; ++j) acc[mt][nt][j] = 0.0f;

    load_tile(0, 0);
    int buf = 0;
    for (int kt = 0; kt < NKT; ++kt) {
        if (kt + 1 < NKT) {
            load_tile(buf ^ 1, kt + 1);
            asm volatile("cp.async.wait_group 1;" ::: "memory");
        } else {
            asm volatile("cp.async.wait_group 0;" ::: "memory");
        }
        __syncthreads();

        #pragma unroll
        for (int ks = 0; ks < 2; ++ks) {
            uint32_t a[2][4];
            #pragma unroll
            for (int mt = 0; mt < 2; ++mt) {
                int row = wm + mt * 16 + (lane & 15);
                int kc  = ks * 16 + ((lane >> 4) << 3);
                ldsm_x4(a[mt][0], a[mt][1], a[mt][2], a[mt][3],
                        smem_u32(&As[buf][row][kc]));
            }
            uint32_t b[8][2];
            #pragma unroll
            for (int jg = 0; jg < 4; ++jg) {
                int row = wn + jg * 16 + (lane & 7) + ((lane >> 4) << 3);
                int kc  = ks * 16 + ((lane >> 3) & 1) * 8;
                ldsm_x4(b[jg*2][0], b[jg*2][1], b[jg*2+1][0], b[jg*2+1][1],
                        smem_u32(&Bs[buf][row][kc]));
            }
            #pragma unroll
            for (int mt = 0; mt < 2; ++mt)
                #pragma unroll
                for (int nt = 0; nt < 8; ++nt)
                    mma16816(acc[mt][nt], a[mt], b[nt]);
        }
        __syncthreads();
        buf ^= 1;
    }

    // epilogue
    #pragma unroll
    for (int mt = 0; mt < 2; ++mt) {
        int r0 = bm + wm + mt * 16 + (lane >> 2);
        #pragma unroll
        for (int nt = 0; nt < 8; ++nt) {
            int col = bn + wn + nt * 8 + (lane & 3) * 2;
            float2 v0 = make_float2(acc[mt][nt][0], acc[mt][nt][1]);
            float2 v1 = make_float2(acc[mt][nt][2], acc[mt][nt][3]);
            if (Res) {
                float2 a0 = *(const float2*)&Res[(size_t)r0 * D_MODEL + col];
                float2 a1 = *(const float2*)&Res[(size_t)(r0 + 8) * D_MODEL + col];
                v0.x += a0.x; v0.y += a0.y; v1.x += a1.x; v1.y += a1.y;
            }
            *(float2*)&C[(size_t)r0 * D_MODEL + col] = v0;
            *(float2*)&C[(size_t)(r0 + 8) * D_MODEL + col] = v1;
        }
    }
}

// ---------------- gate GEMM ----------------
__global__ __launch_bounds__(256)
void gates_kernel(const float* __restrict__ Wi, const float* __restrict__ Wf,
                  const float* __restrict__ Wo)
{
    __shared__ float xs[32][132];
    __shared__ float ws[32][NGATES];
    const int tid = threadIdx.x;
    const int row0 = blockIdx.x * 128;
    const int tx = tid & 15, ty = tid >> 4;
    const int c0 = tx * 3;
    const int r0 = ty * 8;

    float acc[8][3];
    #pragma unroll
    for (int r = 0; r < 8; ++r) { acc[r][0]=0.f; acc[r][1]=0.f; acc[r][2]=0.f; }

    for (int k0 = 0; k0 < D_MODEL; k0 += 32) {
        #pragma unroll
        for (int i = 0; i < 4; ++i) {
            int idx4 = tid + i * 256;
            int r = idx4 >> 3;
            int c4 = (idx4 & 7) << 2;
            float4 v = *(const float4*)(g_xn + (size_t)(row0 + r) * D_MODEL + k0 + c4);
            xs[c4+0][r] = v.x; xs[c4+1][r] = v.y; xs[c4+2][r] = v.z; xs[c4+3][r] = v.w;
        }
        #pragma unroll
        for (int i = 0; i < 6; ++i) {
            int idx = tid + i * 256;
            int j = idx >> 5;
            int kk = idx & 31;
            const float* Wg = (j < 16) ? (Wi + (size_t)j * D_MODEL)
                            : (j < 32) ? (Wf + (size_t)(j - 16) * D_MODEL)
                                       : (Wo + (size_t)(j - 32) * D_MODEL);
            ws[kk][j] = Wg[k0 + kk];
        }
        __syncthreads();
        #pragma unroll
        for (int k = 0; k < 32; ++k) {
            float b0 = ws[k][c0], b1 = ws[k][c0+1], b2 = ws[k][c0+2];
            #pragma unroll
            for (int r = 0; r < 8; ++r) {
                float a = xs[k][r0 + r];
                acc[r][0] = fmaf(a, b0, acc[r][0]);
                acc[r][1] = fmaf(a, b1, acc[r][1]);
                acc[r][2] = fmaf(a, b2, acc[r][2]);
            }
        }
        __syncthreads();
    }
    #pragma unroll
    for (int r = 0; r < 8; ++r) {
        #pragma unroll
        for (int c = 0; c < 3; ++c) {
            float z = acc[r][c];
            float g = GATE_CAP * tanhf(z * (1.0f / GATE_CAP));
            g = 1.0f / (1.0f + expf(-g));
            g_gates[(size_t)(row0 + r0 + r) * NGATES + c0 + c] = g;
        }
    }
}

// ---------------- sequential mLSTM scan ----------------
__global__ __launch_bounds__(64)
void scan_kernel(float* __restrict__ Hfin)
{
    const int h = blockIdx.x;
    const int b = blockIdx.y;
    const int e = threadIdx.x;

    float H[HD];
    #pragma unroll
    for (int d = 0; d < HD; ++d) H[d] = 0.0f;

    __shared__ __align__(16) float sq[HD];
    __shared__ __align__(16) float sk[HD];

    const size_t rbase = (size_t)b * SS;
    const int col = h * HD + e;
    const float* qp = g_q + rbase * D_MODEL + col;
    const float* kp = g_k + rbase * D_MODEL + col;
    const float* vp = g_v + rbase * D_MODEL + col;
    const float* gp = g_gates + rbase * NGATES;
    float* hp = g_h + rbase * D_MODEL + col;

    float qv = qp[0], kv = kp[0], vv = vp[0];
    float ig = gp[h], fg = gp[16 + h], og = gp[32 + h];

    for (int t = 0; t < SS; ++t) {
        sq[e] = qv; sk[e] = kv;
        const float ivv = ig * vv;
        const float fgc = fg;
        const float ogc = og;
        __syncthreads();
        if (t + 1 < SS) {
            size_t o = (size_t)(t + 1) * D_MODEL;
            qv = qp[o]; kv = kp[o]; vv = vp[o];
            int go = (t + 1) * NGATES;
            ig = gp[go + h]; fg = gp[go + 16 + h]; og = gp[go + 32 + h];
        }
        float a0 = 0.f, a1 = 0.f, a2 = 0.f, a3 = 0.f;
        #pragma unroll
        for (int d = 0; d < HD; d += 4) {
            float4 kk = *(const float4*)&sk[d];
            float4 qq = *(const float4*)&sq[d];
            H[d+0] = fmaf(ivv, kk.x, fgc * H[d+0]); a0 = fmaf(qq.x, H[d+0], a0);
            H[d+1] = fmaf(ivv, kk.y, fgc * H[d+1]); a1 = fmaf(qq.y, H[d+1], a1);
            H[d+2] = fmaf(ivv, kk.z, fgc * H[d+2]); a2 = fmaf(qq.z, H[d+2], a2);
            H[d+3] = fmaf(ivv, kk.w, fgc * H[d+3]); a3 = fmaf(qq.w, H[d+3], a3);
        }
        hp[(size_t)t * D_MODEL] = ogc * ((a0 + a1) + (a2 + a3));
        __syncthreads();
    }

    float* Hf = (Hfin ? Hfin : g_Hdump) + (((size_t)b * NH + h) * HD) * HD;
    #pragma unroll
    for (int d = 0; d < HD; ++d) Hf[d * HD + e] = H[d];
}

// ---------------- launcher ----------------
extern "C" void kernel_launch(void* const* d_in, const int* in_sizes, int n_in,
                              void* d_out, int out_size)
{
    const float* x    = (const float*)d_in[0];
    const float* Wq   = (const float*)d_in[1];
    const float* Wk   = (const float*)d_in[2];
    const float* Wv   = (const float*)d_in[3];
    const float* Wi   = (const float*)d_in[4];
    const float* Wf   = (const float*)d_in[5];
    const float* Wo   = (const float*)d_in[6];
    const float* Wout = (const float*)d_in[7];
    const float* lnw  = (const float*)d_in[8];

    float* y = (float*)d_out;
    float* Hfin = ((size_t)out_size >= Y_ELEMS + H_ELEMS) ? (y + Y_ELEMS) : nullptr;

    void *pAxn, *pAh, *pBq, *pBk, *pBv, *pBo, *pXn, *pH, *pQ, *pK, *pV;
    cudaGetSymbolAddress(&pAxn, g_Axn);
    cudaGetSymbolAddress(&pAh,  g_Ah);
    cudaGetSymbolAddress(&pBq,  g_Bq);
    cudaGetSymbolAddress(&pBk,  g_Bk);
    cudaGetSymbolAddress(&pBv,  g_Bv);
    cudaGetSymbolAddress(&pBo,  g_Bo);
    cudaGetSymbolAddress(&pXn,  g_xn);
    cudaGetSymbolAddress(&pH,   g_h);
    cudaGetSymbolAddress(&pQ,   g_q);
    cudaGetSymbolAddress(&pK,   g_k);
    cudaGetSymbolAddress(&pV,   g_v);

    rmsnorm_kernel<<<MROWS, 256>>>(x, lnw);

    convert_hilo_kernel<0><<<(MROWS * 128) / 256, 256>>>((const float*)pXn, (__nv_bfloat16*)pAxn);
    convert_hilo_kernel<1><<<(D_MODEL * 128) / 256, 256>>>(Wq, (__nv_bfloat16*)pBq);
    convert_hilo_kernel<1><<<(D_MODEL * 128) / 256, 256>>>(Wk, (__nv_bfloat16*)pBk);
    convert_hilo_kernel<1><<<(D_MODEL * 128) / 256, 256>>>(Wv, (__nv_bfloat16*)pBv);
    convert_hilo_kernel<1><<<(D_MODEL * 128) / 256, 256>>>(Wout, (__nv_bfloat16*)pBo);

    dim3 ggrid(D_MODEL / BN, MROWS / BM);   // (8, 128)
    gemm_hmma<<<ggrid, 256>>>((const __nv_bfloat16*)pAxn, (const __nv_bfloat16*)pBq, (float*)pQ, nullptr);
    gemm_hmma<<<ggrid, 256>>>((const __nv_bfloat16*)pAxn, (const __nv_bfloat16*)pBk, (float*)pK, nullptr);
    gemm_hmma<<<ggrid, 256>>>((const __nv_bfloat16*)pAxn, (const __nv_bfloat16*)pBv, (float*)pV, nullptr);
    gates_kernel<<<MROWS / 128, 256>>>(Wi, Wf, Wo);

    scan_kernel<<<dim3(NH, BB), 64>>>(Hfin);

    convert_hilo_kernel<0><<<(MROWS * 128) / 256, 256>>>((const float*)pH, (__nv_bfloat16*)pAh);
    gemm_hmma<<<ggrid, 256>>>((const __nv_bfloat16*)pAh, (const __nv_bfloat16*)pBo, y, x);
}

// round 4
// speedup vs baseline: 1.5589x; 1.0790x over previous
#include <cuda_runtime.h>
#include <cuda_bf16.h>
#include <math.h>
#include <cstdint>

// ---------------- problem constants ----------------
constexpr int D_MODEL = 1024;
constexpr int NH      = 16;
constexpr int HD      = 64;
constexpr int BB      = 8;
constexpr int SS      = 2048;
constexpr int MROWS   = BB * SS;          // 16384
constexpr int NGATES  = 48;
constexpr float GATE_CAP = 15.0f;
constexpr float EPS = 1e-5f;

constexpr size_t Y_ELEMS = (size_t)MROWS * D_MODEL;
constexpr size_t H_ELEMS = (size_t)BB * NH * HD * HD;

// split-precision K concat: A' = [hi|lo|hi], B' = [hi|hi|lo]  -> K' = 3072
constexpr int K2 = 3 * D_MODEL;           // 3072
constexpr int NQKV = 3 * D_MODEL;         // fused QKV output width

// GEMM tiling
constexpr int BM = 128, BN = 128, BK = 32;
constexpr int NKT = K2 / BK;              // 96
constexpr int SROW = 40;                  // smem row stride (bf16), conflict-free ldmatrix

// ---------------- device scratch ----------------
__device__ float g_xn[MROWS * D_MODEL];
__device__ float g_qkv[(size_t)MROWS * NQKV];            // 192 MB
__device__ float g_h [MROWS * D_MODEL];
__device__ float g_gates[MROWS * NGATES];
__device__ float g_Hdump[BB * NH * HD * HD];

__device__ __nv_bfloat16 g_Axn [(size_t)MROWS * K2];     // 96 MB
__device__ __nv_bfloat16 g_Ah  [(size_t)MROWS * K2];     // 96 MB
__device__ __nv_bfloat16 g_Bqkv[(size_t)NQKV * K2];      // 18 MB (stacked Wq,Wk,Wv)
__device__ __nv_bfloat16 g_Bo  [(size_t)D_MODEL * K2];   // 6 MB

// ---------------- helpers ----------------
__device__ __forceinline__ uint32_t smem_u32(const void* p) {
    uint32_t a;
    asm("{ .reg .u64 t; cvta.to.shared.u64 t, %1; cvt.u32.u64 %0, t; }" : "=r"(a) : "l"(p));
    return a;
}
__device__ __forceinline__ void cp16(void* sdst, const void* gsrc) {
    uint32_t d = smem_u32(sdst);
    asm volatile("cp.async.cg.shared.global [%0], [%1], 16;" :: "r"(d), "l"(gsrc) : "memory");
}
__device__ __forceinline__ void ldsm_x4(uint32_t& r0, uint32_t& r1, uint32_t& r2, uint32_t& r3,
                                        uint32_t addr) {
    asm volatile("ldmatrix.sync.aligned.m8n8.x4.shared.b16 {%0,%1,%2,%3}, [%4];"
                 : "=r"(r0), "=r"(r1), "=r"(r2), "=r"(r3) : "r"(addr));
}
__device__ __forceinline__ void mma16816(float* c, const uint32_t* a, const uint32_t* b) {
    asm volatile(
        "mma.sync.aligned.m16n8k16.row.col.f32.bf16.bf16.f32 "
        "{%0,%1,%2,%3}, {%4,%5,%6,%7}, {%8,%9}, {%0,%1,%2,%3};"
        : "+f"(c[0]), "+f"(c[1]), "+f"(c[2]), "+f"(c[3])
        : "r"(a[0]), "r"(a[1]), "r"(a[2]), "r"(a[3]), "r"(b[0]), "r"(b[1]));
}

// ---------------- RMSNorm: x -> g_xn ----------------
__global__ __launch_bounds__(256)
void rmsnorm_kernel(const float* __restrict__ x, const float* __restrict__ w)
{
    int row = blockIdx.x;
    int t = threadIdx.x;
    const float4* xr = (const float4*)(x + (size_t)row * D_MODEL);
    float4 v = xr[t];
    float ss = v.x*v.x + v.y*v.y + v.z*v.z + v.w*v.w;
    #pragma unroll
    for (int o = 16; o; o >>= 1) ss += __shfl_xor_sync(0xffffffffu, ss, o);
    __shared__ float sred[8];
    if ((t & 31) == 0) sred[t >> 5] = ss;
    __syncthreads();
    if (t < 8) {
        float s = sred[t];
        #pragma unroll
        for (int o = 4; o; o >>= 1) s += __shfl_xor_sync(0xffu, s, o);
        if (t == 0) sred[0] = s;
    }
    __syncthreads();
    float inv = rsqrtf(sred[0] * (1.0f / D_MODEL) + EPS);
    const float4* wr = (const float4*)w;
    float4 wv = wr[t];
    float4 o4;
    o4.x = v.x * inv * wv.x; o4.y = v.y * inv * wv.y;
    o4.z = v.z * inv * wv.z; o4.w = v.w * inv * wv.w;
    ((float4*)(g_xn + (size_t)row * D_MODEL))[t] = o4;
}

// ---------------- fp32 -> bf16 hi/lo concat along K ----------------
// VARIANT 0 (A-side): [hi | lo | hi]    VARIANT 1 (B-side): [hi | hi | lo]
template<int VARIANT>
__global__ __launch_bounds__(256)
void convert_hilo_kernel(const float* __restrict__ src, __nv_bfloat16* __restrict__ dst)
{
    int idx = blockIdx.x * blockDim.x + threadIdx.x;   // one per 8 elems
    int r   = idx >> 7;
    int k0  = (idx & 127) << 3;
    const float4* sp = (const float4*)(src + (size_t)r * D_MODEL + k0);
    float4 v0 = sp[0], v1 = sp[1];
    float f[8] = {v0.x, v0.y, v0.z, v0.w, v1.x, v1.y, v1.z, v1.w};
    __nv_bfloat16 hi[8], lo[8];
    #pragma unroll
    for (int i = 0; i < 8; ++i) {
        hi[i] = __float2bfloat16(f[i]);
        lo[i] = __float2bfloat16(f[i] - __bfloat162float(hi[i]));
    }
    uint4 H = *(uint4*)hi;
    uint4 L = *(uint4*)lo;
    __nv_bfloat16* rp = dst + (size_t)r * K2 + k0;
    if (VARIANT == 0) {
        *(uint4*)(rp)              = H;
        *(uint4*)(rp + D_MODEL)    = L;
        *(uint4*)(rp + 2*D_MODEL)  = H;
    } else {
        *(uint4*)(rp)              = H;
        *(uint4*)(rp + D_MODEL)    = H;
        *(uint4*)(rp + 2*D_MODEL)  = L;
    }
}

// ---------------- HMMA GEMM: C[M, ldc] = A'[M,K2] * B'[*,K2]^T (+Res) ----------------
// grid (Ncols/BN, M/BM), 256 threads = 8 warps (4m x 2n), warp tile 32x64.
__global__ __launch_bounds__(256, 2)
void gemm_hmma(const __nv_bfloat16* __restrict__ A, const __nv_bfloat16* __restrict__ B,
               float* __restrict__ C, const float* __restrict__ Res, int ldc)
{
    __shared__ __align__(16) __nv_bfloat16 As[2][BM][SROW];
    __shared__ __align__(16) __nv_bfloat16 Bs[2][BN][SROW];

    const int tid = threadIdx.x;
    const int wid = tid >> 5, lane = tid & 31;
    const int bm = blockIdx.y * BM, bn = blockIdx.x * BN;
    const int wm = (wid >> 1) * 32;
    const int wn = (wid & 1) * 64;

    const __nv_bfloat16* Ag = A + (size_t)bm * K2;
    const __nv_bfloat16* Bg = B + (size_t)bn * K2;

    int r0l = tid >> 2;
    int c0l = (tid & 3) * 8;

    auto load_tile = [&](int s, int kt) {
        const __nv_bfloat16* Aa = Ag + (size_t)kt * BK;
        const __nv_bfloat16* Bb = Bg + (size_t)kt * BK;
        #pragma unroll
        for (int i = 0; i < 2; ++i) {
            int r = r0l + i * 64;
            cp16(&As[s][r][c0l], Aa + (size_t)r * K2 + c0l);
            cp16(&Bs[s][r][c0l], Bb + (size_t)r * K2 + c0l);
        }
        asm volatile("cp.async.commit_group;" ::: "memory");
    };

    float acc[2][8][4];
    #pragma unroll
    for (int mt = 0; mt < 2; ++mt)
        #pragma unroll
        for (int nt = 0; nt < 8; ++nt)
            #pragma unroll
            for (int j = 0; j < 4; ++j) acc[mt][nt][j] = 0.0f;

    load_tile(0, 0);
    int buf = 0;
    for (int kt = 0; kt < NKT; ++kt) {
        if (kt + 1 < NKT) {
            load_tile(buf ^ 1, kt + 1);
            asm volatile("cp.async.wait_group 1;" ::: "memory");
        } else {
            asm volatile("cp.async.wait_group 0;" ::: "memory");
        }
        __syncthreads();

        #pragma unroll
        for (int ks = 0; ks < 2; ++ks) {
            uint32_t a[2][4];
            #pragma unroll
            for (int mt = 0; mt < 2; ++mt) {
                int row = wm + mt * 16 + (lane & 15);
                int kc  = ks * 16 + ((lane >> 4) << 3);
                ldsm_x4(a[mt][0], a[mt][1], a[mt][2], a[mt][3],
                        smem_u32(&As[buf][row][kc]));
            }
            uint32_t b[8][2];
            #pragma unroll
            for (int jg = 0; jg < 4; ++jg) {
                int row = wn + jg * 16 + (lane & 7) + ((lane >> 4) << 3);
                int kc  = ks * 16 + ((lane >> 3) & 1) * 8;
                ldsm_x4(b[jg*2][0], b[jg*2][1], b[jg*2+1][0], b[jg*2+1][1],
                        smem_u32(&Bs[buf][row][kc]));
            }
            #pragma unroll
            for (int mt = 0; mt < 2; ++mt)
                #pragma unroll
                for (int nt = 0; nt < 8; ++nt)
                    mma16816(acc[mt][nt], a[mt], b[nt]);
        }
        __syncthreads();
        buf ^= 1;
    }

    #pragma unroll
    for (int mt = 0; mt < 2; ++mt) {
        int r0 = bm + wm + mt * 16 + (lane >> 2);
        #pragma unroll
        for (int nt = 0; nt < 8; ++nt) {
            int col = bn + wn + nt * 8 + (lane & 3) * 2;
            float2 v0 = make_float2(acc[mt][nt][0], acc[mt][nt][1]);
            float2 v1 = make_float2(acc[mt][nt][2], acc[mt][nt][3]);
            if (Res) {
                float2 a0 = *(const float2*)&Res[(size_t)r0 * D_MODEL + col];
                float2 a1 = *(const float2*)&Res[(size_t)(r0 + 8) * D_MODEL + col];
                v0.x += a0.x; v0.y += a0.y; v1.x += a1.x; v1.y += a1.y;
            }
            *(float2*)&C[(size_t)r0 * ldc + col] = v0;
            *(float2*)&C[(size_t)(r0 + 8) * ldc + col] = v1;
        }
    }
}

// ---------------- gate GEMM ----------------
__global__ __launch_bounds__(256)
void gates_kernel(const float* __restrict__ Wi, const float* __restrict__ Wf,
                  const float* __restrict__ Wo)
{
    __shared__ float xs[32][132];
    __shared__ float ws[32][NGATES];
    const int tid = threadIdx.x;
    const int row0 = blockIdx.x * 128;
    const int tx = tid & 15, ty = tid >> 4;
    const int c0 = tx * 3;
    const int r0 = ty * 8;

    float acc[8][3];
    #pragma unroll
    for (int r = 0; r < 8; ++r) { acc[r][0]=0.f; acc[r][1]=0.f; acc[r][2]=0.f; }

    for (int k0 = 0; k0 < D_MODEL; k0 += 32) {
        #pragma unroll
        for (int i = 0; i < 4; ++i) {
            int idx4 = tid + i * 256;
            int r = idx4 >> 3;
            int c4 = (idx4 & 7) << 2;
            float4 v = *(const float4*)(g_xn + (size_t)(row0 + r) * D_MODEL + k0 + c4);
            xs[c4+0][r] = v.x; xs[c4+1][r] = v.y; xs[c4+2][r] = v.z; xs[c4+3][r] = v.w;
        }
        #pragma unroll
        for (int i = 0; i < 6; ++i) {
            int idx = tid + i * 256;
            int j = idx >> 5;
            int kk = idx & 31;
            const float* Wg = (j < 16) ? (Wi + (size_t)j * D_MODEL)
                            : (j < 32) ? (Wf + (size_t)(j - 16) * D_MODEL)
                                       : (Wo + (size_t)(j - 32) * D_MODEL);
            ws[kk][j] = Wg[k0 + kk];
        }
        __syncthreads();
        #pragma unroll
        for (int k = 0; k < 32; ++k) {
            float b0 = ws[k][c0], b1 = ws[k][c0+1], b2 = ws[k][c0+2];
            #pragma unroll
            for (int r = 0; r < 8; ++r) {
                float a = xs[k][r0 + r];
                acc[r][0] = fmaf(a, b0, acc[r][0]);
                acc[r][1] = fmaf(a, b1, acc[r][1]);
                acc[r][2] = fmaf(a, b2, acc[r][2]);
            }
        }
        __syncthreads();
    }
    #pragma unroll
    for (int r = 0; r < 8; ++r) {
        #pragma unroll
        for (int c = 0; c < 3; ++c) {
            float z = acc[r][c];
            float g = GATE_CAP * tanhf(z * (1.0f / GATE_CAP));
            g = 1.0f / (1.0f + expf(-g));
            g_gates[(size_t)(row0 + r0 + r) * NGATES + c0 + c] = g;
        }
    }
}

// ---------------- sequential mLSTM scan, 256 threads ----------------
// grid (NH, BB). thread (e, dg): e = tid>>2 owns column e; dg = tid&3 owns d in [dg*16, dg*16+16).
__global__ __launch_bounds__(256)
void scan_kernel(float* __restrict__ Hfin)
{
    const int h = blockIdx.x;
    const int b = blockIdx.y;
    const int tid = threadIdx.x;
    const int e  = tid >> 2;
    const int dg = tid & 3;
    const int d0 = dg * 16;

    float H[16];
    #pragma unroll
    for (int j = 0; j < 16; ++j) H[j] = 0.0f;

    __shared__ __align__(16) float sq[2][HD];
    __shared__ __align__(16) float sk[2][HD];
    __shared__ float sv[2][HD];
    __shared__ float sg[2][3];

    const size_t rbase = (size_t)b * SS;
    const int colq = h * HD;
    const float* qp = g_qkv + rbase * NQKV + colq;   // q at +0, k at +1024, v at +2048
    const float* gp = g_gates + rbase * NGATES;
    float* hp = g_h + rbase * D_MODEL + colq;

    // prefetch t=0
    float qv = 0.f, kv = 0.f, vvl = 0.f, gv = 0.f;
    if (tid < HD) {
        qv  = qp[tid];
        kv  = qp[D_MODEL + tid];
        vvl = qp[2 * D_MODEL + tid];
    } else if (tid < HD + 3) {
        gv = gp[(tid - HD) * 16 + h];
    }

    for (int t = 0; t < SS; ++t) {
        const int p = t & 1;
        if (tid < HD) { sq[p][tid] = qv; sk[p][tid] = kv; sv[p][tid] = vvl; }
        else if (tid < HD + 3) sg[p][tid - HD] = gv;
        __syncthreads();

        // prefetch t+1 while computing t
        if (t + 1 < SS) {
            size_t o = (size_t)(t + 1) * NQKV;
            if (tid < HD) {
                qv  = qp[o + tid];
                kv  = qp[o + D_MODEL + tid];
                vvl = qp[o + 2 * D_MODEL + tid];
            } else if (tid < HD + 3) {
                gv = gp[(size_t)(t + 1) * NGATES + (tid - HD) * 16 + h];
            }
        }

        const float ig = sg[p][0], fg = sg[p][1], og = sg[p][2];
        const float ivv = ig * sv[p][e];
        float a0 = 0.f, a1 = 0.f;
        #pragma unroll
        for (int j = 0; j < 16; j += 4) {
            float4 kk = *(const float4*)&sk[p][d0 + j];
            float4 qq = *(const float4*)&sq[p][d0 + j];
            H[j+0] = fmaf(ivv, kk.x, fg * H[j+0]); a0 = fmaf(qq.x, H[j+0], a0);
            H[j+1] = fmaf(ivv, kk.y, fg * H[j+1]); a1 = fmaf(qq.y, H[j+1], a1);
            H[j+2] = fmaf(ivv, kk.z, fg * H[j+2]); a0 = fmaf(qq.z, H[j+2], a0);
            H[j+3] = fmaf(ivv, kk.w, fg * H[j+3]); a1 = fmaf(qq.w, H[j+3], a1);
        }
        float a = a0 + a1;
        a += __shfl_xor_sync(0xffffffffu, a, 1);
        a += __shfl_xor_sync(0xffffffffu, a, 2);
        if (dg == 0) hp[(size_t)t * D_MODEL + e] = og * a;
        // double-buffered smem: one sync per step is sufficient
    }

    float* Hf = (Hfin ? Hfin : g_Hdump) + ((size_t)(b * NH + h)) * HD * HD;
    #pragma unroll
    for (int j = 0; j < 16; ++j) Hf[(size_t)(d0 + j) * HD + e] = H[j];
}

// ---------------- launcher ----------------
extern "C" void kernel_launch(void* const* d_in, const int* in_sizes, int n_in,
                              void* d_out, int out_size)
{
    const float* x    = (const float*)d_in[0];
    const float* Wq   = (const float*)d_in[1];
    const float* Wk   = (const float*)d_in[2];
    const float* Wv   = (const float*)d_in[3];
    const float* Wi   = (const float*)d_in[4];
    const float* Wf   = (const float*)d_in[5];
    const float* Wo   = (const float*)d_in[6];
    const float* Wout = (const float*)d_in[7];
    const float* lnw  = (const float*)d_in[8];

    float* y = (float*)d_out;
    float* Hfin = ((size_t)out_size >= Y_ELEMS + H_ELEMS) ? (y + Y_ELEMS) : nullptr;

    void *pAxn, *pAh, *pBqkv, *pBo, *pXn, *pH, *pQKV;
    cudaGetSymbolAddress(&pAxn,  g_Axn);
    cudaGetSymbolAddress(&pAh,   g_Ah);
    cudaGetSymbolAddress(&pBqkv, g_Bqkv);
    cudaGetSymbolAddress(&pBo,   g_Bo);
    cudaGetSymbolAddress(&pXn,   g_xn);
    cudaGetSymbolAddress(&pH,    g_h);
    cudaGetSymbolAddress(&pQKV,  g_qkv);

    rmsnorm_kernel<<<MROWS, 256>>>(x, lnw);

    convert_hilo_kernel<0><<<(MROWS * 128) / 256, 256>>>((const float*)pXn, (__nv_bfloat16*)pAxn);
    convert_hilo_kernel<1><<<(D_MODEL * 128) / 256, 256>>>(Wq, (__nv_bfloat16*)pBqkv);
    convert_hilo_kernel<1><<<(D_MODEL * 128) / 256, 256>>>(Wk, (__nv_bfloat16*)pBqkv + (size_t)D_MODEL * K2);
    convert_hilo_kernel<1><<<(D_MODEL * 128) / 256, 256>>>(Wv, (__nv_bfloat16*)pBqkv + (size_t)2 * D_MODEL * K2);
    convert_hilo_kernel<1><<<(D_MODEL * 128) / 256, 256>>>(Wout, (__nv_bfloat16*)pBo);

    // fused QKV GEMM: C = [Q|K|V], N = 3072
    gemm_hmma<<<dim3(NQKV / BN, MROWS / BM), 256>>>(
        (const __nv_bfloat16*)pAxn, (const __nv_bfloat16*)pBqkv, (float*)pQKV, nullptr, NQKV);
    gates_kernel<<<MROWS / 128, 256>>>(Wi, Wf, Wo);

    scan_kernel<<<dim3(NH, BB), 256>>>(Hfin);

    convert_hilo_kernel<0><<<(MROWS * 128) / 256, 256>>>((const float*)pH, (__nv_bfloat16*)pAh);
    gemm_hmma<<<dim3(D_MODEL / BN, MROWS / BM), 256>>>(
        (const __nv_bfloat16*)pAh, (const __nv_bfloat16*)pBo, y, x, D_MODEL);
}

// round 5
// speedup vs baseline: 1.7206x; 1.1037x over previous
#include <cuda_runtime.h>
#include <cuda_bf16.h>
#include <math.h>
#include <cstdint>

// ---------------- problem constants ----------------
constexpr int D_MODEL = 1024;
constexpr int NH      = 16;
constexpr int HD      = 64;
constexpr int BB      = 8;
constexpr int SS      = 2048;
constexpr int MROWS   = BB * SS;          // 16384
constexpr int NGATES  = 48;
constexpr float GATE_CAP = 15.0f;
constexpr float EPS = 1e-5f;

constexpr size_t Y_ELEMS = (size_t)MROWS * D_MODEL;
constexpr size_t H_ELEMS = (size_t)BB * NH * HD * HD;

// split-precision K concat: A' = [hi|lo|hi], B' = [hi|hi|lo]  -> K' = 3072
constexpr int K2 = 3 * D_MODEL;           // 3072
constexpr int NQKV = 3 * D_MODEL;         // fused QKV output width

// GEMM tiling
constexpr int BM = 128, BN = 128, BK = 32;
constexpr int NKT = K2 / BK;              // 96
constexpr int SROW = 40;                  // smem row stride (bf16), conflict-free ldmatrix

// scan pipeline
constexpr int PF    = 6;                  // prefetch depth
constexpr int NRING = 8;                  // ring slots (> PF so no second sync)

// ---------------- device scratch ----------------
__device__ float g_xn[MROWS * D_MODEL];
__device__ float g_qkv[(size_t)MROWS * NQKV];            // 192 MB
__device__ float g_h [MROWS * D_MODEL];
__device__ float g_gates[MROWS * NGATES];
__device__ float g_Hdump[BB * NH * HD * HD];

__device__ __nv_bfloat16 g_Axn [(size_t)MROWS * K2];     // 96 MB
__device__ __nv_bfloat16 g_Ah  [(size_t)MROWS * K2];     // 96 MB
__device__ __nv_bfloat16 g_Bqkv[(size_t)NQKV * K2];      // 18 MB (stacked Wq,Wk,Wv)
__device__ __nv_bfloat16 g_Bo  [(size_t)D_MODEL * K2];   // 6 MB

// ---------------- helpers ----------------
__device__ __forceinline__ uint32_t smem_u32(const void* p) {
    uint32_t a;
    asm("{ .reg .u64 t; cvta.to.shared.u64 t, %1; cvt.u32.u64 %0, t; }" : "=r"(a) : "l"(p));
    return a;
}
__device__ __forceinline__ void cp16(void* sdst, const void* gsrc) {
    uint32_t d = smem_u32(sdst);
    asm volatile("cp.async.cg.shared.global [%0], [%1], 16;" :: "r"(d), "l"(gsrc) : "memory");
}
__device__ __forceinline__ void cp4(void* sdst, const void* gsrc) {
    uint32_t d = smem_u32(sdst);
    asm volatile("cp.async.ca.shared.global [%0], [%1], 4;" :: "r"(d), "l"(gsrc) : "memory");
}
__device__ __forceinline__ void ldsm_x4(uint32_t& r0, uint32_t& r1, uint32_t& r2, uint32_t& r3,
                                        uint32_t addr) {
    asm volatile("ldmatrix.sync.aligned.m8n8.x4.shared.b16 {%0,%1,%2,%3}, [%4];"
                 : "=r"(r0), "=r"(r1), "=r"(r2), "=r"(r3) : "r"(addr));
}
__device__ __forceinline__ void mma16816(float* c, const uint32_t* a, const uint32_t* b) {
    asm volatile(
        "mma.sync.aligned.m16n8k16.row.col.f32.bf16.bf16.f32 "
        "{%0,%1,%2,%3}, {%4,%5,%6,%7}, {%8,%9}, {%0,%1,%2,%3};"
        : "+f"(c[0]), "+f"(c[1]), "+f"(c[2]), "+f"(c[3])
        : "r"(a[0]), "r"(a[1]), "r"(a[2]), "r"(a[3]), "r"(b[0]), "r"(b[1]));
}

// ---------------- RMSNorm: x -> g_xn ----------------
__global__ __launch_bounds__(256)
void rmsnorm_kernel(const float* __restrict__ x, const float* __restrict__ w)
{
    int row = blockIdx.x;
    int t = threadIdx.x;
    const float4* xr = (const float4*)(x + (size_t)row * D_MODEL);
    float4 v = xr[t];
    float ss = v.x*v.x + v.y*v.y + v.z*v.z + v.w*v.w;
    #pragma unroll
    for (int o = 16; o; o >>= 1) ss += __shfl_xor_sync(0xffffffffu, ss, o);
    __shared__ float sred[8];
    if ((t & 31) == 0) sred[t >> 5] = ss;
    __syncthreads();
    if (t < 8) {
        float s = sred[t];
        #pragma unroll
        for (int o = 4; o; o >>= 1) s += __shfl_xor_sync(0xffu, s, o);
        if (t == 0) sred[0] = s;
    }
    __syncthreads();
    float inv = rsqrtf(sred[0] * (1.0f / D_MODEL) + EPS);
    const float4* wr = (const float4*)w;
    float4 wv = wr[t];
    float4 o4;
    o4.x = v.x * inv * wv.x; o4.y = v.y * inv * wv.y;
    o4.z = v.z * inv * wv.z; o4.w = v.w * inv * wv.w;
    ((float4*)(g_xn + (size_t)row * D_MODEL))[t] = o4;
}

// ---------------- fp32 -> bf16 hi/lo concat along K ----------------
// VARIANT 0 (A-side): [hi | lo | hi]    VARIANT 1 (B-side): [hi | hi | lo]
template<int VARIANT>
__global__ __launch_bounds__(256)
void convert_hilo_kernel(const float* __restrict__ src, __nv_bfloat16* __restrict__ dst)
{
    int idx = blockIdx.x * blockDim.x + threadIdx.x;   // one per 8 elems
    int r   = idx >> 7;
    int k0  = (idx & 127) << 3;
    const float4* sp = (const float4*)(src + (size_t)r * D_MODEL + k0);
    float4 v0 = sp[0], v1 = sp[1];
    float f[8] = {v0.x, v0.y, v0.z, v0.w, v1.x, v1.y, v1.z, v1.w};
    __nv_bfloat16 hi[8], lo[8];
    #pragma unroll
    for (int i = 0; i < 8; ++i) {
        hi[i] = __float2bfloat16(f[i]);
        lo[i] = __float2bfloat16(f[i] - __bfloat162float(hi[i]));
    }
    uint4 H = *(uint4*)hi;
    uint4 L = *(uint4*)lo;
    __nv_bfloat16* rp = dst + (size_t)r * K2 + k0;
    if (VARIANT == 0) {
        *(uint4*)(rp)              = H;
        *(uint4*)(rp + D_MODEL)    = L;
        *(uint4*)(rp + 2*D_MODEL)  = H;
    } else {
        *(uint4*)(rp)              = H;
        *(uint4*)(rp + D_MODEL)    = H;
        *(uint4*)(rp + 2*D_MODEL)  = L;
    }
}

// ---------------- HMMA GEMM: C[M, ldc] = A'[M,K2] * B'[*,K2]^T (+Res) ----------------
__global__ __launch_bounds__(256, 2)
void gemm_hmma(const __nv_bfloat16* __restrict__ A, const __nv_bfloat16* __restrict__ B,
               float* __restrict__ C, const float* __restrict__ Res, int ldc)
{
    __shared__ __align__(16) __nv_bfloat16 As[2][BM][SROW];
    __shared__ __align__(16) __nv_bfloat16 Bs[2][BN][SROW];

    const int tid = threadIdx.x;
    const int wid = tid >> 5, lane = tid & 31;
    const int bm = blockIdx.y * BM, bn = blockIdx.x * BN;
    const int wm = (wid >> 1) * 32;
    const int wn = (wid & 1) * 64;

    const __nv_bfloat16* Ag = A + (size_t)bm * K2;
    const __nv_bfloat16* Bg = B + (size_t)bn * K2;

    int r0l = tid >> 2;
    int c0l = (tid & 3) * 8;

    auto load_tile = [&](int s, int kt) {
        const __nv_bfloat16* Aa = Ag + (size_t)kt * BK;
        const __nv_bfloat16* Bb = Bg + (size_t)kt * BK;
        #pragma unroll
        for (int i = 0; i < 2; ++i) {
            int r = r0l + i * 64;
            cp16(&As[s][r][c0l], Aa + (size_t)r * K2 + c0l);
            cp16(&Bs[s][r][c0l], Bb + (size_t)r * K2 + c0l);
        }
        asm volatile("cp.async.commit_group;" ::: "memory");
    };

    float acc[2][8][4];
    #pragma unroll
    for (int mt = 0; mt < 2; ++mt)
        #pragma unroll
        for (int nt = 0; nt < 8; ++nt)
            #pragma unroll
            for (int j = 0; j < 4; ++j) acc[mt][nt][j] = 0.0f;

    load_tile(0, 0);
    int buf = 0;
    for (int kt = 0; kt < NKT; ++kt) {
        if (kt + 1 < NKT) {
            load_tile(buf ^ 1, kt + 1);
            asm volatile("cp.async.wait_group 1;" ::: "memory");
        } else {
            asm volatile("cp.async.wait_group 0;" ::: "memory");
        }
        __syncthreads();

        #pragma unroll
        for (int ks = 0; ks < 2; ++ks) {
            uint32_t a[2][4];
            #pragma unroll
            for (int mt = 0; mt < 2; ++mt) {
                int row = wm + mt * 16 + (lane & 15);
                int kc  = ks * 16 + ((lane >> 4) << 3);
                ldsm_x4(a[mt][0], a[mt][1], a[mt][2], a[mt][3],
                        smem_u32(&As[buf][row][kc]));
            }
            uint32_t b[8][2];
            #pragma unroll
            for (int jg = 0; jg < 4; ++jg) {
                int row = wn + jg * 16 + (lane & 7) + ((lane >> 4) << 3);
                int kc  = ks * 16 + ((lane >> 3) & 1) * 8;
                ldsm_x4(b[jg*2][0], b[jg*2][1], b[jg*2+1][0], b[jg*2+1][1],
                        smem_u32(&Bs[buf][row][kc]));
            }
            #pragma unroll
            for (int mt = 0; mt < 2; ++mt)
                #pragma unroll
                for (int nt = 0; nt < 8; ++nt)
                    mma16816(acc[mt][nt], a[mt], b[nt]);
        }
        __syncthreads();
        buf ^= 1;
    }

    #pragma unroll
    for (int mt = 0; mt < 2; ++mt) {
        int r0 = bm + wm + mt * 16 + (lane >> 2);
        #pragma unroll
        for (int nt = 0; nt < 8; ++nt) {
            int col = bn + wn + nt * 8 + (lane & 3) * 2;
            float2 v0 = make_float2(acc[mt][nt][0], acc[mt][nt][1]);
            float2 v1 = make_float2(acc[mt][nt][2], acc[mt][nt][3]);
            if (Res) {
                float2 a0 = *(const float2*)&Res[(size_t)r0 * D_MODEL + col];
                float2 a1 = *(const float2*)&Res[(size_t)(r0 + 8) * D_MODEL + col];
                v0.x += a0.x; v0.y += a0.y; v1.x += a1.x; v1.y += a1.y;
            }
            *(float2*)&C[(size_t)r0 * ldc + col] = v0;
            *(float2*)&C[(size_t)(r0 + 8) * ldc + col] = v1;
        }
    }
}

// ---------------- gate GEMM ----------------
__global__ __launch_bounds__(256)
void gates_kernel(const float* __restrict__ Wi, const float* __restrict__ Wf,
                  const float* __restrict__ Wo)
{
    __shared__ float xs[32][132];
    __shared__ float ws[32][NGATES];
    const int tid = threadIdx.x;
    const int row0 = blockIdx.x * 128;
    const int tx = tid & 15, ty = tid >> 4;
    const int c0 = tx * 3;
    const int r0 = ty * 8;

    float acc[8][3];
    #pragma unroll
    for (int r = 0; r < 8; ++r) { acc[r][0]=0.f; acc[r][1]=0.f; acc[r][2]=0.f; }

    for (int k0 = 0; k0 < D_MODEL; k0 += 32) {
        #pragma unroll
        for (int i = 0; i < 4; ++i) {
            int idx4 = tid + i * 256;
            int r = idx4 >> 3;
            int c4 = (idx4 & 7) << 2;
            float4 v = *(const float4*)(g_xn + (size_t)(row0 + r) * D_MODEL + k0 + c4);
            xs[c4+0][r] = v.x; xs[c4+1][r] = v.y; xs[c4+2][r] = v.z; xs[c4+3][r] = v.w;
        }
        #pragma unroll
        for (int i = 0; i < 6; ++i) {
            int idx = tid + i * 256;
            int j = idx >> 5;
            int kk = idx & 31;
            const float* Wg = (j < 16) ? (Wi + (size_t)j * D_MODEL)
                            : (j < 32) ? (Wf + (size_t)(j - 16) * D_MODEL)
                                       : (Wo + (size_t)(j - 32) * D_MODEL);
            ws[kk][j] = Wg[k0 + kk];
        }
        __syncthreads();
        #pragma unroll
        for (int k = 0; k < 32; ++k) {
            float b0 = ws[k][c0], b1 = ws[k][c0+1], b2 = ws[k][c0+2];
            #pragma unroll
            for (int r = 0; r < 8; ++r) {
                float a = xs[k][r0 + r];
                acc[r][0] = fmaf(a, b0, acc[r][0]);
                acc[r][1] = fmaf(a, b1, acc[r][1]);
                acc[r][2] = fmaf(a, b2, acc[r][2]);
            }
        }
        __syncthreads();
    }
    #pragma unroll
    for (int r = 0; r < 8; ++r) {
        #pragma unroll
        for (int c = 0; c < 3; ++c) {
            float z = acc[r][c];
            float g = GATE_CAP * tanhf(z * (1.0f / GATE_CAP));
            g = 1.0f / (1.0f + expf(-g));
            g_gates[(size_t)(row0 + r0 + r) * NGATES + c0 + c] = g;
        }
    }
}

// ---------------- sequential mLSTM scan: deep cp.async pipeline ----------------
// grid (NH, BB), 256 threads. thread (e = tid>>2) owns column e; dg = tid&3 owns 16 d-values.
__global__ __launch_bounds__(256)
void scan_kernel(float* __restrict__ Hfin)
{
    const int h = blockIdx.x;
    const int b = blockIdx.y;
    const int tid = threadIdx.x;
    const int e  = tid >> 2;
    const int dg = tid & 3;
    const int d0 = dg * 16;

    struct __align__(16) Stage { float q[HD]; float k[HD]; float v[HD]; float g[4]; };
    __shared__ Stage st[NRING];

    const size_t rbase = (size_t)b * SS;
    const int colq = h * HD;
    const float* qp = g_qkv + rbase * NQKV + colq;   // q at +0, k at +1024, v at +2048
    const float* gp = g_gates + rbase * NGATES;
    float* hp = g_h + rbase * D_MODEL + colq;

    // stage loader: 48 threads move q/k/v (16B each), 3 threads move gates
    auto issue = [&](int t) {
        if (t < SS) {
            Stage& s = st[t & (NRING - 1)];
            size_t o = (size_t)t * NQKV;
            if (tid < 16)      cp16(&s.q[tid * 4],        qp + o + tid * 4);
            else if (tid < 32) cp16(&s.k[(tid - 16) * 4], qp + o + D_MODEL + (tid - 16) * 4);
            else if (tid < 48) cp16(&s.v[(tid - 32) * 4], qp + o + 2 * D_MODEL + (tid - 32) * 4);
            else if (tid < 51) cp4(&s.g[tid - 48], gp + (size_t)t * NGATES + (tid - 48) * 16 + h);
        }
        asm volatile("cp.async.commit_group;" ::: "memory");
    };

    #pragma unroll
    for (int t = 0; t < PF; ++t) issue(t);

    float H[16];
    #pragma unroll
    for (int j = 0; j < 16; ++j) H[j] = 0.0f;

    for (int t = 0; t < SS; ++t) {
        asm volatile("cp.async.wait_group %0;" :: "n"(PF - 1) : "memory");
        __syncthreads();                           // stage t visible to all threads
        issue(t + PF);                             // slot (t+PF)&7 last read at step t-2: safe

        const Stage& s = st[t & (NRING - 1)];
        const float ig = s.g[0], fg = s.g[1], og = s.g[2];
        const float ivv = ig * s.v[e];
        float a0 = 0.f, a1 = 0.f;
        #pragma unroll
        for (int j = 0; j < 16; j += 4) {
            float4 kk = *(const float4*)&s.k[d0 + j];
            float4 qq = *(const float4*)&s.q[d0 + j];
            H[j+0] = fmaf(ivv, kk.x, fg * H[j+0]); a0 = fmaf(qq.x, H[j+0], a0);
            H[j+1] = fmaf(ivv, kk.y, fg * H[j+1]); a1 = fmaf(qq.y, H[j+1], a1);
            H[j+2] = fmaf(ivv, kk.z, fg * H[j+2]); a0 = fmaf(qq.z, H[j+2], a0);
            H[j+3] = fmaf(ivv, kk.w, fg * H[j+3]); a1 = fmaf(qq.w, H[j+3], a1);
        }
        float a = a0 + a1;
        a += __shfl_xor_sync(0xffffffffu, a, 1);
        a += __shfl_xor_sync(0xffffffffu, a, 2);
        if (dg == 0) hp[(size_t)t * D_MODEL + e] = og * a;
    }

    float* Hf = (Hfin ? Hfin : g_Hdump) + ((size_t)(b * NH + h)) * HD * HD;
    #pragma unroll
    for (int j = 0; j < 16; ++j) Hf[(size_t)(d0 + j) * HD + e] = H[j];
}

// ---------------- launcher ----------------
extern "C" void kernel_launch(void* const* d_in, const int* in_sizes, int n_in,
                              void* d_out, int out_size)
{
    const float* x    = (const float*)d_in[0];
    const float* Wq   = (const float*)d_in[1];
    const float* Wk   = (const float*)d_in[2];
    const float* Wv   = (const float*)d_in[3];
    const float* Wi   = (const float*)d_in[4];
    const float* Wf   = (const float*)d_in[5];
    const float* Wo   = (const float*)d_in[6];
    const float* Wout = (const float*)d_in[7];
    const float* lnw  = (const float*)d_in[8];

    float* y = (float*)d_out;
    float* Hfin = ((size_t)out_size >= Y_ELEMS + H_ELEMS) ? (y + Y_ELEMS) : nullptr;

    void *pAxn, *pAh, *pBqkv, *pBo, *pXn, *pH, *pQKV;
    cudaGetSymbolAddress(&pAxn,  g_Axn);
    cudaGetSymbolAddress(&pAh,   g_Ah);
    cudaGetSymbolAddress(&pBqkv, g_Bqkv);
    cudaGetSymbolAddress(&pBo,   g_Bo);
    cudaGetSymbolAddress(&pXn,   g_xn);
    cudaGetSymbolAddress(&pH,    g_h);
    cudaGetSymbolAddress(&pQKV,  g_qkv);

    // launch order chosen so ncu (-s 5 -c 1, 0-indexed launch 5) profiles the fused QKV GEMM
    rmsnorm_kernel<<<MROWS, 256>>>(x, lnw);                                                     // 0
    convert_hilo_kernel<0><<<(MROWS * 128) / 256, 256>>>((const float*)pXn, (__nv_bfloat16*)pAxn); // 1
    convert_hilo_kernel<1><<<(D_MODEL * 128) / 256, 256>>>(Wq, (__nv_bfloat16*)pBqkv);             // 2
    convert_hilo_kernel<1><<<(D_MODEL * 128) / 256, 256>>>(Wk, (__nv_bfloat16*)pBqkv + (size_t)D_MODEL * K2);     // 3
    convert_hilo_kernel<1><<<(D_MODEL * 128) / 256, 256>>>(Wv, (__nv_bfloat16*)pBqkv + (size_t)2 * D_MODEL * K2); // 4

    gemm_hmma<<<dim3(NQKV / BN, MROWS / BM), 256>>>(                                             // 5 <- profiled
        (const __nv_bfloat16*)pAxn, (const __nv_bfloat16*)pBqkv, (float*)pQKV, nullptr, NQKV);

    gates_kernel<<<MROWS / 128, 256>>>(Wi, Wf, Wo);                                              // 6
    scan_kernel<<<dim3(NH, BB), 256>>>(Hfin);                                                    // 7

    convert_hilo_kernel<1><<<(D_MODEL * 128) / 256, 256>>>(Wout, (__nv_bfloat16*)pBo);           // 8
    convert_hilo_kernel<0><<<(MROWS * 128) / 256, 256>>>((const float*)pH, (__nv_bfloat16*)pAh); // 9
    gemm_hmma<<<dim3(D_MODEL / BN, MROWS / BM), 256>>>(                                          // 10
        (const __nv_bfloat16*)pAh, (const __nv_bfloat16*)pBo, y, x, D_MODEL);
}

// round 6
// speedup vs baseline: 2.0190x; 1.1734x over previous
#include <cuda_runtime.h>
#include <cuda_fp16.h>
#include <math.h>
#include <cstdint>

// ---------------- problem constants ----------------
constexpr int D_MODEL = 1024;
constexpr int NH      = 16;
constexpr int HD      = 64;
constexpr int BB      = 8;
constexpr int SS      = 2048;
constexpr int MROWS   = BB * SS;          // 16384
constexpr int NGATES  = 48;
constexpr float GATE_CAP = 15.0f;
constexpr float EPS = 1e-5f;

constexpr size_t Y_ELEMS = (size_t)MROWS * D_MODEL;
constexpr size_t H_ELEMS = (size_t)BB * NH * HD * HD;

// fp16 split-precision, 2-term: A' = [hi|lo], B' = [hi|hi]  -> K' = 2048
// C = (Ahi+Alo)·Bhi = A·Bhi ; dropped A·Blo ~ 2^-12 relative
constexpr int K2 = 2 * D_MODEL;           // 2048
constexpr int NQKV = 3 * D_MODEL;         // fused QKV output width

// GEMM tiling
constexpr int BM = 128, BN = 128, BK = 32;
constexpr int NKT = K2 / BK;              // 64
constexpr int SROW = 40;                  // smem row stride (halves), conflict-free ldmatrix

// scan pipeline
constexpr int PF    = 6;                  // prefetch depth
constexpr int NRING = 8;                  // ring slots (> PF so no second sync)

// ---------------- device scratch ----------------
__device__ float g_xn[MROWS * D_MODEL];                  // fp32 xn (for gates)
__device__ float g_qkv[(size_t)MROWS * NQKV];            // 192 MB
__device__ float g_gates[MROWS * NGATES];
__device__ float g_Hdump[BB * NH * HD * HD];

__device__ __half g_Axn [(size_t)MROWS * K2];            // 64 MB  [hi|lo]
__device__ __half g_Ah  [(size_t)MROWS * K2];            // 64 MB  [hi|lo] (written by scan)
__device__ __half g_Bqkv[(size_t)NQKV * K2];             // 12 MB  [hi|hi] stacked Wq,Wk,Wv
__device__ __half g_Bo  [(size_t)D_MODEL * K2];          // 4 MB   [hi|hi]

// ---------------- helpers ----------------
__device__ __forceinline__ uint32_t smem_u32(const void* p) {
    uint32_t a;
    asm("{ .reg .u64 t; cvta.to.shared.u64 t, %1; cvt.u32.u64 %0, t; }" : "=r"(a) : "l"(p));
    return a;
}
__device__ __forceinline__ void cp16(void* sdst, const void* gsrc) {
    uint32_t d = smem_u32(sdst);
    asm volatile("cp.async.cg.shared.global [%0], [%1], 16;" :: "r"(d), "l"(gsrc) : "memory");
}
__device__ __forceinline__ void cp4(void* sdst, const void* gsrc) {
    uint32_t d = smem_u32(sdst);
    asm volatile("cp.async.ca.shared.global [%0], [%1], 4;" :: "r"(d), "l"(gsrc) : "memory");
}
__device__ __forceinline__ void ldsm_x4(uint32_t& r0, uint32_t& r1, uint32_t& r2, uint32_t& r3,
                                        uint32_t addr) {
    asm volatile("ldmatrix.sync.aligned.m8n8.x4.shared.b16 {%0,%1,%2,%3}, [%4];"
                 : "=r"(r0), "=r"(r1), "=r"(r2), "=r"(r3) : "r"(addr));
}
__device__ __forceinline__ void mma16816(float* c, const uint32_t* a, const uint32_t* b) {
    asm volatile(
        "mma.sync.aligned.m16n8k16.row.col.f32.f16.f16.f32 "
        "{%0,%1,%2,%3}, {%4,%5,%6,%7}, {%8,%9}, {%0,%1,%2,%3};"
        : "+f"(c[0]), "+f"(c[1]), "+f"(c[2]), "+f"(c[3])
        : "r"(a[0]), "r"(a[1]), "r"(a[2]), "r"(a[3]), "r"(b[0]), "r"(b[1]));
}

// ---------------- RMSNorm: x -> g_xn (fp32) + g_Axn ([hi|lo] fp16) ----------------
__global__ __launch_bounds__(256)
void rmsnorm_kernel(const float* __restrict__ x, const float* __restrict__ w)
{
    int row = blockIdx.x;
    int t = threadIdx.x;
    const float4* xr = (const float4*)(x + (size_t)row * D_MODEL);
    float4 v = xr[t];
    float ss = v.x*v.x + v.y*v.y + v.z*v.z + v.w*v.w;
    #pragma unroll
    for (int o = 16; o; o >>= 1) ss += __shfl_xor_sync(0xffffffffu, ss, o);
    __shared__ float sred[8];
    if ((t & 31) == 0) sred[t >> 5] = ss;
    __syncthreads();
    if (t < 8) {
        float s = sred[t];
        #pragma unroll
        for (int o = 4; o; o >>= 1) s += __shfl_xor_sync(0xffu, s, o);
        if (t == 0) sred[0] = s;
    }
    __syncthreads();
    float inv = rsqrtf(sred[0] * (1.0f / D_MODEL) + EPS);
    const float4* wr = (const float4*)w;
    float4 wv = wr[t];
    float f[4];
    f[0] = v.x * inv * wv.x; f[1] = v.y * inv * wv.y;
    f[2] = v.z * inv * wv.z; f[3] = v.w * inv * wv.w;
    *(float4*)(g_xn + (size_t)row * D_MODEL + t * 4) = make_float4(f[0], f[1], f[2], f[3]);

    __half hi[4], lo[4];
    #pragma unroll
    for (int i = 0; i < 4; ++i) {
        hi[i] = __float2half(f[i]);
        lo[i] = __float2half(f[i] - __half2float(hi[i]));
    }
    __half* rp = g_Axn + (size_t)row * K2 + t * 4;
    *(uint2*)(rp)           = *(uint2*)hi;
    *(uint2*)(rp + D_MODEL) = *(uint2*)lo;
}

// ---------------- weight fp32 -> fp16 [hi|hi] ----------------
__global__ __launch_bounds__(256)
void convert_whh_kernel(const float* __restrict__ src, __half* __restrict__ dst)
{
    int idx = blockIdx.x * blockDim.x + threadIdx.x;   // one per 8 elems
    int r   = idx >> 7;
    int k0  = (idx & 127) << 3;
    const float4* sp = (const float4*)(src + (size_t)r * D_MODEL + k0);
    float4 v0 = sp[0], v1 = sp[1];
    float f[8] = {v0.x, v0.y, v0.z, v0.w, v1.x, v1.y, v1.z, v1.w};
    __half hi[8];
    #pragma unroll
    for (int i = 0; i < 8; ++i) hi[i] = __float2half(f[i]);
    uint4 H = *(uint4*)hi;
    __half* rp = dst + (size_t)r * K2 + k0;
    *(uint4*)(rp)           = H;
    *(uint4*)(rp + D_MODEL) = H;
}

// ---------------- HMMA GEMM: C[M, ldc] = A'[M,K2] * B'[*,K2]^T (+Res) ----------------
__global__ __launch_bounds__(256, 2)
void gemm_hmma(const __half* __restrict__ A, const __half* __restrict__ B,
               float* __restrict__ C, const float* __restrict__ Res, int ldc)
{
    __shared__ __align__(16) __half As[2][BM][SROW];
    __shared__ __align__(16) __half Bs[2][BN][SROW];

    const int tid = threadIdx.x;
    const int wid = tid >> 5, lane = tid & 31;
    const int bm = blockIdx.y * BM, bn = blockIdx.x * BN;
    const int wm = (wid >> 1) * 32;
    const int wn = (wid & 1) * 64;

    const __half* Ag = A + (size_t)bm * K2;
    const __half* Bg = B + (size_t)bn * K2;

    int r0l = tid >> 2;
    int c0l = (tid & 3) * 8;

    auto load_tile = [&](int s, int kt) {
        const __half* Aa = Ag + (size_t)kt * BK;
        const __half* Bb = Bg + (size_t)kt * BK;
        #pragma unroll
        for (int i = 0; i < 2; ++i) {
            int r = r0l + i * 64;
            cp16(&As[s][r][c0l], Aa + (size_t)r * K2 + c0l);
            cp16(&Bs[s][r][c0l], Bb + (size_t)r * K2 + c0l);
        }
        asm volatile("cp.async.commit_group;" ::: "memory");
    };

    float acc[2][8][4];
    #pragma unroll
    for (int mt = 0; mt < 2; ++mt)
        #pragma unroll
        for (int nt = 0; nt < 8; ++nt)
            #pragma unroll
            for (int j = 0; j < 4; ++j) acc[mt][nt][j] = 0.0f;

    load_tile(0, 0);
    int buf = 0;
    for (int kt = 0; kt < NKT; ++kt) {
        if (kt + 1 < NKT) {
            load_tile(buf ^ 1, kt + 1);
            asm volatile("cp.async.wait_group 1;" ::: "memory");
        } else {
            asm volatile("cp.async.wait_group 0;" ::: "memory");
        }
        __syncthreads();

        #pragma unroll
        for (int ks = 0; ks < 2; ++ks) {
            uint32_t a[2][4];
            #pragma unroll
            for (int mt = 0; mt < 2; ++mt) {
                int row = wm + mt * 16 + (lane & 15);
                int kc  = ks * 16 + ((lane >> 4) << 3);
                ldsm_x4(a[mt][0], a[mt][1], a[mt][2], a[mt][3],
                        smem_u32(&As[buf][row][kc]));
            }
            uint32_t b[8][2];
            #pragma unroll
            for (int jg = 0; jg < 4; ++jg) {
                int row = wn + jg * 16 + (lane & 7) + ((lane >> 4) << 3);
                int kc  = ks * 16 + ((lane >> 3) & 1) * 8;
                ldsm_x4(b[jg*2][0], b[jg*2][1], b[jg*2+1][0], b[jg*2+1][1],
                        smem_u32(&Bs[buf][row][kc]));
            }
            #pragma unroll
            for (int mt = 0; mt < 2; ++mt)
                #pragma unroll
                for (int nt = 0; nt < 8; ++nt)
                    mma16816(acc[mt][nt], a[mt], b[nt]);
        }
        __syncthreads();
        buf ^= 1;
    }

    #pragma unroll
    for (int mt = 0; mt < 2; ++mt) {
        int r0 = bm + wm + mt * 16 + (lane >> 2);
        #pragma unroll
        for (int nt = 0; nt < 8; ++nt) {
            int col = bn + wn + nt * 8 + (lane & 3) * 2;
            float2 v0 = make_float2(acc[mt][nt][0], acc[mt][nt][1]);
            float2 v1 = make_float2(acc[mt][nt][2], acc[mt][nt][3]);
            if (Res) {
                float2 a0 = *(const float2*)&Res[(size_t)r0 * D_MODEL + col];
                float2 a1 = *(const float2*)&Res[(size_t)(r0 + 8) * D_MODEL + col];
                v0.x += a0.x; v0.y += a0.y; v1.x += a1.x; v1.y += a1.y;
            }
            *(float2*)&C[(size_t)r0 * ldc + col] = v0;
            *(float2*)&C[(size_t)(r0 + 8) * ldc + col] = v1;
        }
    }
}

// ---------------- gate GEMM ----------------
__global__ __launch_bounds__(256)
void gates_kernel(const float* __restrict__ Wi, const float* __restrict__ Wf,
                  const float* __restrict__ Wo)
{
    __shared__ float xs[32][132];
    __shared__ float ws[32][NGATES];
    const int tid = threadIdx.x;
    const int row0 = blockIdx.x * 128;
    const int tx = tid & 15, ty = tid >> 4;
    const int c0 = tx * 3;
    const int r0 = ty * 8;

    float acc[8][3];
    #pragma unroll
    for (int r = 0; r < 8; ++r) { acc[r][0]=0.f; acc[r][1]=0.f; acc[r][2]=0.f; }

    for (int k0 = 0; k0 < D_MODEL; k0 += 32) {
        #pragma unroll
        for (int i = 0; i < 4; ++i) {
            int idx4 = tid + i * 256;
            int r = idx4 >> 3;
            int c4 = (idx4 & 7) << 2;
            float4 v = *(const float4*)(g_xn + (size_t)(row0 + r) * D_MODEL + k0 + c4);
            xs[c4+0][r] = v.x; xs[c4+1][r] = v.y; xs[c4+2][r] = v.z; xs[c4+3][r] = v.w;
        }
        #pragma unroll
        for (int i = 0; i < 6; ++i) {
            int idx = tid + i * 256;
            int j = idx >> 5;
            int kk = idx & 31;
            const float* Wg = (j < 16) ? (Wi + (size_t)j * D_MODEL)
                            : (j < 32) ? (Wf + (size_t)(j - 16) * D_MODEL)
                                       : (Wo + (size_t)(j - 32) * D_MODEL);
            ws[kk][j] = Wg[k0 + kk];
        }
        __syncthreads();
        #pragma unroll
        for (int k = 0; k < 32; ++k) {
            float b0 = ws[k][c0], b1 = ws[k][c0+1], b2 = ws[k][c0+2];
            #pragma unroll
            for (int r = 0; r < 8; ++r) {
                float a = xs[k][r0 + r];
                acc[r][0] = fmaf(a, b0, acc[r][0]);
                acc[r][1] = fmaf(a, b1, acc[r][1]);
                acc[r][2] = fmaf(a, b2, acc[r][2]);
            }
        }
        __syncthreads();
    }
    #pragma unroll
    for (int r = 0; r < 8; ++r) {
        #pragma unroll
        for (int c = 0; c < 3; ++c) {
            float z = acc[r][c];
            float g = GATE_CAP * tanhf(z * (1.0f / GATE_CAP));
            g = 1.0f / (1.0f + expf(-g));
            g_gates[(size_t)(row0 + r0 + r) * NGATES + c0 + c] = g;
        }
    }
}

// ---------------- sequential mLSTM scan: deep cp.async pipeline ----------------
// grid (NH, BB), 256 threads. e = tid>>2 owns column e; dg = tid&3 owns 16 d-values.
// Writes h directly as fp16 [hi|lo] into g_Ah.
__global__ __launch_bounds__(256)
void scan_kernel(float* __restrict__ Hfin)
{
    const int h = blockIdx.x;
    const int b = blockIdx.y;
    const int tid = threadIdx.x;
    const int e  = tid >> 2;
    const int dg = tid & 3;
    const int d0 = dg * 16;

    struct __align__(16) Stage { float q[HD]; float k[HD]; float v[HD]; float g[4]; };
    __shared__ Stage st[NRING];

    const size_t rbase = (size_t)b * SS;
    const int colq = h * HD;
    const float* qp = g_qkv + rbase * NQKV + colq;   // q at +0, k at +1024, v at +2048
    const float* gp = g_gates + rbase * NGATES;
    __half* hp = g_Ah + rbase * K2 + colq;           // hi at +0, lo at +1024

    auto issue = [&](int t) {
        if (t < SS) {
            Stage& s = st[t & (NRING - 1)];
            size_t o = (size_t)t * NQKV;
            if (tid < 16)      cp16(&s.q[tid * 4],        qp + o + tid * 4);
            else if (tid < 32) cp16(&s.k[(tid - 16) * 4], qp + o + D_MODEL + (tid - 16) * 4);
            else if (tid < 48) cp16(&s.v[(tid - 32) * 4], qp + o + 2 * D_MODEL + (tid - 32) * 4);
            else if (tid < 51) cp4(&s.g[tid - 48], gp + (size_t)t * NGATES + (tid - 48) * 16 + h);
        }
        asm volatile("cp.async.commit_group;" ::: "memory");
    };

    #pragma unroll
    for (int t = 0; t < PF; ++t) issue(t);

    float H[16];
    #pragma unroll
    for (int j = 0; j < 16; ++j) H[j] = 0.0f;

    for (int t = 0; t < SS; ++t) {
        asm volatile("cp.async.wait_group %0;" :: "n"(PF - 1) : "memory");
        __syncthreads();
        issue(t + PF);

        const Stage& s = st[t & (NRING - 1)];
        const float ig = s.g[0], fg = s.g[1], og = s.g[2];
        const float ivv = ig * s.v[e];
        float a0 = 0.f, a1 = 0.f;
        #pragma unroll
        for (int j = 0; j < 16; j += 4) {
            float4 kk = *(const float4*)&s.k[d0 + j];
            float4 qq = *(const float4*)&s.q[d0 + j];
            H[j+0] = fmaf(ivv, kk.x, fg * H[j+0]); a0 = fmaf(qq.x, H[j+0], a0);
            H[j+1] = fmaf(ivv, kk.y, fg * H[j+1]); a1 = fmaf(qq.y, H[j+1], a1);
            H[j+2] = fmaf(ivv, kk.z, fg * H[j+2]); a0 = fmaf(qq.z, H[j+2], a0);
            H[j+3] = fmaf(ivv, kk.w, fg * H[j+3]); a1 = fmaf(qq.w, H[j+3], a1);
        }
        float a = a0 + a1;
        a += __shfl_xor_sync(0xffffffffu, a, 1);
        a += __shfl_xor_sync(0xffffffffu, a, 2);
        if (dg == 0) {
            float hv = og * a;
            __half hh = __float2half(hv);
            __half hl = __float2half(hv - __half2float(hh));
            hp[(size_t)t * K2 + e]           = hh;
            hp[(size_t)t * K2 + D_MODEL + e] = hl;
        }
    }

    float* Hf = (Hfin ? Hfin : g_Hdump) + ((size_t)(b * NH + h)) * HD * HD;
    #pragma unroll
    for (int j = 0; j < 16; ++j) Hf[(size_t)(d0 + j) * HD + e] = H[j];
}

// ---------------- launcher ----------------
extern "C" void kernel_launch(void* const* d_in, const int* in_sizes, int n_in,
                              void* d_out, int out_size)
{
    const float* x    = (const float*)d_in[0];
    const float* Wq   = (const float*)d_in[1];
    const float* Wk   = (const float*)d_in[2];
    const float* Wv   = (const float*)d_in[3];
    const float* Wi   = (const float*)d_in[4];
    const float* Wf   = (const float*)d_in[5];
    const float* Wo   = (const float*)d_in[6];
    const float* Wout = (const float*)d_in[7];
    const float* lnw  = (const float*)d_in[8];

    float* y = (float*)d_out;
    float* Hfin = ((size_t)out_size >= Y_ELEMS + H_ELEMS) ? (y + Y_ELEMS) : nullptr;

    void *pAxn, *pAh, *pBqkv, *pBo, *pQKV;
    cudaGetSymbolAddress(&pAxn,  g_Axn);
    cudaGetSymbolAddress(&pAh,   g_Ah);
    cudaGetSymbolAddress(&pBqkv, g_Bqkv);
    cudaGetSymbolAddress(&pBo,   g_Bo);
    cudaGetSymbolAddress(&pQKV,  g_qkv);

    rmsnorm_kernel<<<MROWS, 256>>>(x, lnw);
    convert_whh_kernel<<<(D_MODEL * 128) / 256, 256>>>(Wq, (__half*)pBqkv);
    convert_whh_kernel<<<(D_MODEL * 128) / 256, 256>>>(Wk, (__half*)pBqkv + (size_t)D_MODEL * K2);
    convert_whh_kernel<<<(D_MODEL * 128) / 256, 256>>>(Wv, (__half*)pBqkv + (size_t)2 * D_MODEL * K2);
    convert_whh_kernel<<<(D_MODEL * 128) / 256, 256>>>(Wout, (__half*)pBo);

    // fused QKV GEMM: C = [Q|K|V], N = 3072
    gemm_hmma<<<dim3(NQKV / BN, MROWS / BM), 256>>>(
        (const __half*)pAxn, (const __half*)pBqkv, (float*)pQKV, nullptr, NQKV);
    gates_kernel<<<MROWS / 128, 256>>>(Wi, Wf, Wo);

    scan_kernel<<<dim3(NH, BB), 256>>>(Hfin);

    gemm_hmma<<<dim3(D_MODEL / BN, MROWS / BM), 256>>>(
        (const __half*)pAh, (const __half*)pBo, y, x, D_MODEL);
}